// round 11
// baseline (speedup 1.0000x reference)
#include <cuda_runtime.h>
#include <cuda_bf16.h>
#include <math.h>
#include <stdint.h>

#define T_STEPS 1024
#define NBATCH  128
#define NU      512
#define DIN     128
#define EPSF    0.01f
#define SCAN_CTAS 128
#define HSZ     (NBATCH * NU)
#define Z_SMEM (128 * 132 * 4 + 128 * 64 * 4)

// scan smem word offsets (all 4-byte words)
#define W_WFH   0                 // weight hi frags: 32kt*8ng*32lane*2r = 16384
#define W_WFL   16384             // weight lo frags: 16384
#define W_HFH   32768             // h hi frags: 4096
#define W_HFL   36864             // h lo frags: 4096
#define W_STG   40960             // stage: stgA[2][544] + stgW[2][544] = 2176
#define SCAN_SMEM_WORDS (40960 + 2176)
#define SCAN_SMEM_BYTES (SCAN_SMEM_WORDS * 4)   // 172544 B

// ---------------- device scratch --------------------------------------------
__device__ float g_z[(size_t)T_STEPS * NU * NBATCH];  // [t][j][b]
__device__ float g_h[2 * HSZ];                        // fp32 h (epilogue only)
__device__ uint2 g_hf[2][8][4096];                    // frag exchange [parity][bb][wd]
__device__ unsigned g_bar_count;
__device__ volatile unsigned g_bar_phase;

// ---------------- fallback grid barrier --------------------------------------
__device__ __forceinline__ void grid_barrier() {
    __syncthreads();
    if (threadIdx.x == 0) {
        unsigned ph = g_bar_phase;
        __threadfence();
        if (atomicAdd(&g_bar_count, 1u) == SCAN_CTAS - 1u) {
            atomicExch(&g_bar_count, 0u);
            __threadfence();
            g_bar_phase = ph + 1u;
        } else {
            while (g_bar_phase == ph) { __nanosleep(32); }
        }
        __threadfence();
    }
    __syncthreads();
}

// ---------------- z precompute: z[t][j][b] -----------------------------------
__global__ void __launch_bounds__(256) z_kernel(const float* __restrict__ x,
                                                const float* __restrict__ Ew,
                                                const float* __restrict__ Eb) {
    extern __shared__ float sm[];
    float* xs = sm;              // [128][132]
    float* ew = sm + 128 * 132;  // [128][64]
    const int t   = blockIdx.x;
    const int tid = threadIdx.x;

    for (int idx = tid; idx < 128 * 32; idx += 256) {
        int b  = idx >> 5;
        int kq = idx & 31;
        float4 v = *(const float4*)(x + ((size_t)b * T_STEPS + t) * DIN + kq * 4);
        *(float4*)(xs + b * 132 + kq * 4) = v;
    }

    const int bg = tid >> 3;
    const int jg = tid & 7;
    const int b0 = bg * 4;
    const int j0 = jg * 8;

    for (int jb = 0; jb < 8; jb++) {
        __syncthreads();
        for (int idx = tid; idx < 128 * 16; idx += 256) {
            int k  = idx >> 4;
            int jq = idx & 15;
            *(float4*)(ew + k * 64 + jq * 4) =
                *(const float4*)(Ew + (size_t)k * NU + jb * 64 + jq * 4);
        }
        __syncthreads();

        float acc[4][8];
        #pragma unroll
        for (int r = 0; r < 4; r++)
            #pragma unroll
            for (int jj = 0; jj < 8; jj++) acc[r][jj] = 0.f;

        #pragma unroll 2
        for (int k = 0; k < 128; k += 4) {
            float4 xv[4];
            #pragma unroll
            for (int r = 0; r < 4; r++)
                xv[r] = *(const float4*)(xs + (b0 + r) * 132 + k);
            #pragma unroll
            for (int kk = 0; kk < 4; kk++) {
                float4 e0 = *(const float4*)(ew + (k + kk) * 64 + j0);
                float4 e1 = *(const float4*)(ew + (k + kk) * 64 + j0 + 4);
                #pragma unroll
                for (int r = 0; r < 4; r++) {
                    float xk = (kk == 0) ? xv[r].x : (kk == 1) ? xv[r].y
                             : (kk == 2) ? xv[r].z : xv[r].w;
                    acc[r][0] += xk * e0.x;  acc[r][1] += xk * e0.y;
                    acc[r][2] += xk * e0.z;  acc[r][3] += xk * e0.w;
                    acc[r][4] += xk * e1.x;  acc[r][5] += xk * e1.y;
                    acc[r][6] += xk * e1.z;  acc[r][7] += xk * e1.w;
                }
            }
        }

        #pragma unroll
        for (int jj = 0; jj < 8; jj++) {
            int j = jb * 64 + j0 + jj;
            float bias = Eb[j];
            float4 v = make_float4(acc[0][jj] + bias, acc[1][jj] + bias,
                                   acc[2][jj] + bias, acc[3][jj] + bias);
            *(float4*)(g_z + ((size_t)t * NU + j) * NBATCH + b0) = v;
        }
    }
}

// ---------------- HMMA scan: 8 clusters x 16 CTAs, 512 threads ---------------
// Warp w: ng = w>>1 (n-group: A' cols ng*4..+3 and W cols ng*4..+3),
//         kh = w&1  (K half: kt = kh*16 .. +15).
// Weights pre-staged as B-frag words in smem (hi/lo); h frags as in R10.
// 3 independent accumulator chains (hh/lh/hl), depth 16 each.
__device__ __forceinline__ void mma16816(float& d0, float& d1, float& d2, float& d3,
                                         unsigned a0, unsigned a1, unsigned a2, unsigned a3,
                                         unsigned b0, unsigned b1) {
    asm volatile(
        "mma.sync.aligned.m16n8k16.row.col.f32.bf16.bf16.f32 "
        "{%0,%1,%2,%3}, {%4,%5,%6,%7}, {%8,%9}, {%0,%1,%2,%3};"
        : "+f"(d0), "+f"(d1), "+f"(d2), "+f"(d3)
        : "r"(a0), "r"(a1), "r"(a2), "r"(a3), "r"(b0), "r"(b1));
}

template <bool CLU>
__global__ void __launch_bounds__(512, 1) scan_kernel(const float* __restrict__ Bm,
                                                      const float* __restrict__ Cm,
                                                      const float* __restrict__ Dw,
                                                      const float* __restrict__ Db,
                                                      float* __restrict__ out) {
    extern __shared__ unsigned smw[];
    unsigned* wfH = smw + W_WFH;
    unsigned* wfL = smw + W_WFL;
    unsigned* hfH = smw + W_HFH;
    unsigned* hfL = smw + W_HFL;
    float*    stgA0 = (float*)(smw + W_STG);
    float*    stgA1 = stgA0 + 544;
    float*    stgW0 = stgA1 + 544;
    float*    stgW1 = stgW0 + 544;

    const int cta  = blockIdx.x;
    const int bb   = cta >> 4;
    const int col0 = (cta & 15) * 32;
    const int tid  = threadIdx.x;
    const int w    = tid >> 5;
    const int lane = tid & 31;
    const int ng   = w >> 1;
    const int kh   = w & 1;
    const int kt0  = kh * 16;

    // ---- build weight B-frags into smem (one-time; R8-verified layout) ------
    {
        const int nv  = lane >> 2;          // 0..7 virtual col within group
        const int mat = nv >> 2;            // 0: A', 1: W
        const int jw  = col0 + ng * 4 + (nv & 3);
        for (int i = 0; i < 16; i++) {
            int kt = kt0 + i;
            #pragma unroll
            for (int r = 0; r < 2; r++) {
                float v[2];
                #pragma unroll
                for (int e = 0; e < 2; e++) {
                    int k = kt * 16 + r * 8 + (lane & 3) * 2 + e;
                    float d = (k == jw) ? 0.01f : 0.0f;
                    v[e] = (mat == 0)
                         ? EPSF * (Bm[(size_t)k * NU + jw] - 0.6f * Bm[(size_t)jw * NU + k] - d)
                         : (Cm[(size_t)k * NU + jw] - 0.6f * Cm[(size_t)jw * NU + k] - d);
                }
                __nv_bfloat162 hi = __float22bfloat162_rn(make_float2(v[0], v[1]));
                float2 hf = make_float2(__low2float(hi), __high2float(hi));
                __nv_bfloat162 lo = __float22bfloat162_rn(make_float2(v[0] - hf.x, v[1] - hf.y));
                int idx = ((kt * 8 + ng) * 32 + lane) * 2 + r;
                wfH[idx] = *reinterpret_cast<unsigned*>(&hi);
                wfL[idx] = *reinterpret_cast<unsigned*>(&lo);
            }
        }
    }

    // ---- init: zero h frag tiles (h0 = 0) -----------------------------------
    for (int i = tid; i < 4096; i += 512) { hfH[i] = 0u; hfL[i] = 0u; }
    __syncthreads();

    // pointwise ownership: thread -> (b = tid>>5, j = lane); one scalar each
    const int pb  = tid >> 5;
    const int pj  = lane;
    const int pbg = bb * 16 + pb;
    const int pjg = col0 + pj;
    // frag word index for the (pb, even col pair) this lane-pair produces
    const int pje = pjg & ~1;           // even global col of the pair
    const int wdx = (pje >> 4) * 128
                  + ((((pb & 7) << 2) | ((pje >> 1) & 3)) << 2)
                  + ((pb >> 3) | (((pje >> 3) & 1) << 1));

    // D frag coords
    const int m0 = lane >> 2;
    const int c0 = (lane & 3) * 2;
    float* stg_d = (c0 < 4) ? (kh ? stgA1 : stgA0) : (kh ? stgW1 : stgW0);
    const int jd = ng * 4 + (c0 & 3);

    float hold = 0.f;                    // register-carried h (h0 = 0)

    for (int t = 0; t < T_STEPS; t++) {
        // prefetch z (overlaps MMA)
        float zv = __ldcg(g_z + ((size_t)t * NU + pjg) * NBATCH + pbg);

        // ---- MMA mainloop: 3 chains, 16 kt each -----------------------------
        float hh0 = 0.f, hh1 = 0.f, hh2 = 0.f, hh3 = 0.f;
        float lh0 = 0.f, lh1 = 0.f, lh2 = 0.f, lh3 = 0.f;
        float hl0 = 0.f, hl1 = 0.f, hl2 = 0.f, hl3 = 0.f;
        #pragma unroll
        for (int i = 0; i < 16; i++) {
            int kt = kt0 + i;
            uint4 aH = *(const uint4*)&hfH[(kt * 32 + lane) * 4];
            uint4 aL = *(const uint4*)&hfL[(kt * 32 + lane) * 4];
            uint2 bH = *(const uint2*)&wfH[((kt * 8 + ng) * 32 + lane) * 2];
            uint2 bL = *(const uint2*)&wfL[((kt * 8 + ng) * 32 + lane) * 2];
            mma16816(hh0, hh1, hh2, hh3, aH.x, aH.y, aH.z, aH.w, bH.x, bH.y);
            mma16816(lh0, lh1, lh2, lh3, aL.x, aL.y, aL.z, aL.w, bH.x, bH.y);
            mma16816(hl0, hl1, hl2, hl3, aH.x, aH.y, aH.z, aH.w, bL.x, bL.y);
        }
        float d0 = hh0 + lh0 + hl0;
        float d1 = hh1 + lh1 + hl1;
        float d2 = hh2 + lh2 + hl2;
        float d3 = hh3 + lh3 + hl3;

        // ---- stage D --------------------------------------------------------
        stg_d[jd * 17 + m0]           = d0;
        stg_d[(jd + 1) * 17 + m0]     = d1;
        stg_d[jd * 17 + m0 + 8]       = d2;
        stg_d[(jd + 1) * 17 + m0 + 8] = d3;
        __syncthreads();

        // ---- pointwise update (sum both K halves) ---------------------------
        {
            float da = stgA0[pj * 17 + pb] + stgA1[pj * 17 + pb];
            float dw = stgW0[pj * 17 + pb] + stgW1[pj * 17 + pb];
            hold = hold + da + EPSF * tanhf(dw + zv);

            float hnext = __shfl_down_sync(0xffffffffu, hold, 1);
            if ((lane & 1) == 0) {
                __nv_bfloat162 hi = __float22bfloat162_rn(make_float2(hold, hnext));
                __nv_bfloat162 lo = __float22bfloat162_rn(
                    make_float2(hold - __low2float(hi), hnext - __high2float(hi)));
                uint2 wv;
                wv.x = *reinterpret_cast<unsigned*>(&hi);
                wv.y = *reinterpret_cast<unsigned*>(&lo);
                g_hf[t & 1][bb][wdx] = wv;
            }
            if (t == T_STEPS - 1) {
                g_h[HSZ + (size_t)pbg * NU + pjg] = hold;
            }
        }

        if (CLU) {
            asm volatile("barrier.cluster.arrive.aligned;" ::: "memory");
            asm volatile("barrier.cluster.wait.aligned;" ::: "memory");
        } else {
            grid_barrier();
        }

        // ---- reload frag tiles: pure copy -----------------------------------
        if (t < T_STEPS - 1) {
            const uint2* src = &g_hf[t & 1][bb][0];
            #pragma unroll
            for (int it = 0; it < 8; it++) {
                int wd = it * 512 + tid;
                uint2 v = __ldcg(src + wd);
                hfH[wd] = v.x;
                hfL[wd] = v.y;
            }
        }
        __syncthreads();
    }

    // ---------------- epilogue: out[b] = h_final[b] @ Dw + Db ----------------
    {
        const int b = cta;
        const float* hf = g_h + HSZ + (size_t)b * NU;
        float part[10];
        #pragma unroll
        for (int c = 0; c < 10; c++) part[c] = 0.f;
        for (int k = tid; k < NU; k += 512) {
            float hv = __ldcg(hf + k);
            #pragma unroll
            for (int c = 0; c < 10; c++) part[c] += hv * Dw[k * 10 + c];
        }
        __syncthreads();
        float* red = (float*)wfH;   // reuse weight region
        #pragma unroll
        for (int c = 0; c < 10; c++) red[c * 512 + tid] = part[c];
        __syncthreads();
        if (tid < 10) {
            float s = Db[tid];
            for (int i = 0; i < 512; i++) s += red[tid * 512 + i];
            out[b * 10 + tid] = s;
        }
    }
}

// ---------------- launch ------------------------------------------------------
extern "C" void kernel_launch(void* const* d_in, const int* in_sizes, int n_in,
                              void* d_out, int out_size) {
    const float* x  = (const float*)d_in[0];
    const float* B  = (const float*)d_in[1];
    const float* C  = (const float*)d_in[2];
    const float* Ew = (const float*)d_in[3];
    const float* Eb = (const float*)d_in[4];
    const float* Dw = (const float*)d_in[5];
    const float* Db = (const float*)d_in[6];
    float* outp = (float*)d_out;

    cudaFuncSetAttribute(z_kernel, cudaFuncAttributeMaxDynamicSharedMemorySize, Z_SMEM);
    cudaFuncSetAttribute(scan_kernel<true>, cudaFuncAttributeMaxDynamicSharedMemorySize, SCAN_SMEM_BYTES);
    cudaFuncSetAttribute(scan_kernel<true>, cudaFuncAttributeNonPortableClusterSizeAllowed, 1);
    cudaFuncSetAttribute(scan_kernel<false>, cudaFuncAttributeMaxDynamicSharedMemorySize, SCAN_SMEM_BYTES);

    z_kernel<<<T_STEPS, 256, Z_SMEM>>>(x, Ew, Eb);

    cudaLaunchConfig_t cfg = {};
    cfg.gridDim  = dim3(SCAN_CTAS, 1, 1);
    cfg.blockDim = dim3(512, 1, 1);
    cfg.dynamicSmemBytes = SCAN_SMEM_BYTES;
    cfg.stream = 0;
    cudaLaunchAttribute at[1];
    at[0].id = cudaLaunchAttributeClusterDimension;
    at[0].val.clusterDim.x = 16;
    at[0].val.clusterDim.y = 1;
    at[0].val.clusterDim.z = 1;
    cfg.attrs = at;
    cfg.numAttrs = 1;

    int ncl = 0;
    cudaError_t qe = cudaOccupancyMaxActiveClusters(&ncl, scan_kernel<true>, &cfg);
    if (qe == cudaSuccess && ncl >= 1) {
        cudaLaunchKernelEx(&cfg, scan_kernel<true>, B, C, Dw, Db, outp);
    } else {
        cudaGetLastError();
        scan_kernel<false><<<SCAN_CTAS, 512, SCAN_SMEM_BYTES>>>(B, C, Dw, Db, outp);
    }
}

// round 12
// speedup vs baseline: 1.6125x; 1.6125x over previous
#include <cuda_runtime.h>
#include <cuda_bf16.h>
#include <math.h>
#include <stdint.h>

#define T_STEPS 1024
#define NBATCH  128
#define NU      512
#define DIN     128
#define EPSF    0.01f
#define SCAN_CTAS 128
#define HSZ     (NBATCH * NU)
#define Z_SMEM (128 * 132 * 4 + 128 * 64 * 4)

// ---------------- device scratch --------------------------------------------
__device__ float g_z[(size_t)T_STEPS * NU * NBATCH];  // [t][j][b]
__device__ float g_h[2 * HSZ];                        // fp32 h (epilogue only)
__device__ uint2 g_hf[2][8][4096];                    // frag exchange [parity][bb][wd]
__device__ unsigned g_bar_count;
__device__ volatile unsigned g_bar_phase;

// ---------------- fallback grid barrier --------------------------------------
__device__ __forceinline__ void grid_barrier() {
    __syncthreads();
    if (threadIdx.x == 0) {
        unsigned ph = g_bar_phase;
        __threadfence();
        if (atomicAdd(&g_bar_count, 1u) == SCAN_CTAS - 1u) {
            atomicExch(&g_bar_count, 0u);
            __threadfence();
            g_bar_phase = ph + 1u;
        } else {
            while (g_bar_phase == ph) { __nanosleep(32); }
        }
        __threadfence();
    }
    __syncthreads();
}

// ---------------- z precompute: z[t][j][b] -----------------------------------
__global__ void __launch_bounds__(256) z_kernel(const float* __restrict__ x,
                                                const float* __restrict__ Ew,
                                                const float* __restrict__ Eb) {
    extern __shared__ float sm[];
    float* xs = sm;              // [128][132]
    float* ew = sm + 128 * 132;  // [128][64]
    const int t   = blockIdx.x;
    const int tid = threadIdx.x;

    for (int idx = tid; idx < 128 * 32; idx += 256) {
        int b  = idx >> 5;
        int kq = idx & 31;
        float4 v = *(const float4*)(x + ((size_t)b * T_STEPS + t) * DIN + kq * 4);
        *(float4*)(xs + b * 132 + kq * 4) = v;
    }

    const int bg = tid >> 3;
    const int jg = tid & 7;
    const int b0 = bg * 4;
    const int j0 = jg * 8;

    for (int jb = 0; jb < 8; jb++) {
        __syncthreads();
        for (int idx = tid; idx < 128 * 16; idx += 256) {
            int k  = idx >> 4;
            int jq = idx & 15;
            *(float4*)(ew + k * 64 + jq * 4) =
                *(const float4*)(Ew + (size_t)k * NU + jb * 64 + jq * 4);
        }
        __syncthreads();

        float acc[4][8];
        #pragma unroll
        for (int r = 0; r < 4; r++)
            #pragma unroll
            for (int jj = 0; jj < 8; jj++) acc[r][jj] = 0.f;

        #pragma unroll 2
        for (int k = 0; k < 128; k += 4) {
            float4 xv[4];
            #pragma unroll
            for (int r = 0; r < 4; r++)
                xv[r] = *(const float4*)(xs + (b0 + r) * 132 + k);
            #pragma unroll
            for (int kk = 0; kk < 4; kk++) {
                float4 e0 = *(const float4*)(ew + (k + kk) * 64 + j0);
                float4 e1 = *(const float4*)(ew + (k + kk) * 64 + j0 + 4);
                #pragma unroll
                for (int r = 0; r < 4; r++) {
                    float xk = (kk == 0) ? xv[r].x : (kk == 1) ? xv[r].y
                             : (kk == 2) ? xv[r].z : xv[r].w;
                    acc[r][0] += xk * e0.x;  acc[r][1] += xk * e0.y;
                    acc[r][2] += xk * e0.z;  acc[r][3] += xk * e0.w;
                    acc[r][4] += xk * e1.x;  acc[r][5] += xk * e1.y;
                    acc[r][6] += xk * e1.z;  acc[r][7] += xk * e1.w;
                }
            }
        }

        #pragma unroll
        for (int jj = 0; jj < 8; jj++) {
            int j = jb * 64 + j0 + jj;
            float bias = Eb[j];
            float4 v = make_float4(acc[0][jj] + bias, acc[1][jj] + bias,
                                   acc[2][jj] + bias, acc[3][jj] + bias);
            *(float4*)(g_z + ((size_t)t * NU + j) * NBATCH + b0) = v;
        }
    }
}

// ---------------- HMMA scan: 8 clusters x 16 CTAs, 256 threads ---------------
// Warp w = (cg = w>>1, kh = w&1): cols [cg*8, cg*8+8) via 2 n-frags, K half
// kt = kh*16..+15.  Weights in REGISTERS (128/thread, same as R8/R10).
// Exchange/hold identical to R10 (verified).
__device__ __forceinline__ void mma16816(float& d0, float& d1, float& d2, float& d3,
                                         unsigned a0, unsigned a1, unsigned a2, unsigned a3,
                                         unsigned b0, unsigned b1) {
    asm volatile(
        "mma.sync.aligned.m16n8k16.row.col.f32.bf16.bf16.f32 "
        "{%0,%1,%2,%3}, {%4,%5,%6,%7}, {%8,%9}, {%0,%1,%2,%3};"
        : "+f"(d0), "+f"(d1), "+f"(d2), "+f"(d3)
        : "r"(a0), "r"(a1), "r"(a2), "r"(a3), "r"(b0), "r"(b1));
}

template <bool CLU>
__global__ void __launch_bounds__(256, 1) scan_kernel(const float* __restrict__ Bm,
                                                      const float* __restrict__ Cm,
                                                      const float* __restrict__ Dw,
                                                      const float* __restrict__ Db,
                                                      float* __restrict__ out) {
    __shared__ float    stgA[2][32 * 17];    // [kh][j_local][b] A' partials
    __shared__ float    stgW[2][32 * 17];    // [kh][j_local][b] W partials
    __shared__ unsigned hfH[4096];           // h hi frags  [kt][lane][reg]
    __shared__ unsigned hfL[4096];           // h lo frags

    const int cta  = blockIdx.x;
    const int bb   = cta >> 4;
    const int col0 = (cta & 15) * 32;
    const int tid  = threadIdx.x;
    const int w    = tid >> 5;
    const int lane = tid & 31;
    const int cg   = w >> 1;
    const int kh   = w & 1;
    const int kt0  = kh * 16;

    // ---- build this thread's weight B-fragments (2 frags x 16 kt) -----------
    const int nv  = lane >> 2;          // 0..7 virtual col
    const int mat = nv >> 2;            // 0: A', 1: W
    unsigned wH[2][16][2], wL[2][16][2];
    #pragma unroll
    for (int f = 0; f < 2; f++) {
        const int jw = col0 + cg * 8 + f * 4 + (nv & 3);
        #pragma unroll
        for (int i = 0; i < 16; i++) {
            int kt = kt0 + i;
            #pragma unroll
            for (int r = 0; r < 2; r++) {
                float v[2];
                #pragma unroll
                for (int e = 0; e < 2; e++) {
                    int k = kt * 16 + r * 8 + (lane & 3) * 2 + e;
                    float d = (k == jw) ? 0.01f : 0.0f;
                    v[e] = (mat == 0)
                         ? EPSF * (Bm[(size_t)k * NU + jw] - 0.6f * Bm[(size_t)jw * NU + k] - d)
                         : (Cm[(size_t)k * NU + jw] - 0.6f * Cm[(size_t)jw * NU + k] - d);
                }
                __nv_bfloat162 hi = __float22bfloat162_rn(make_float2(v[0], v[1]));
                float2 hf = make_float2(__low2float(hi), __high2float(hi));
                __nv_bfloat162 lo = __float22bfloat162_rn(make_float2(v[0] - hf.x, v[1] - hf.y));
                wH[f][i][r] = *reinterpret_cast<unsigned*>(&hi);
                wL[f][i][r] = *reinterpret_cast<unsigned*>(&lo);
            }
        }
    }

    // ---- init: zero h frag tiles (h0 = 0) -----------------------------------
    for (int i = tid; i < 4096; i += 256) { hfH[i] = 0u; hfL[i] = 0u; }
    __syncthreads();

    // pointwise ownership (R10): thread -> (b = tid>>4, j0 = (tid&15)*2)
    const int pb  = tid >> 4;
    const int pj0 = (tid & 15) * 2;
    const int pbg = bb * 16 + pb;
    const int pjg = col0 + pj0;

    // frag word index for this thread's (pb, pjg) pair (R10-verified inverse)
    const int wdx = (pjg >> 4) * 128
                  + ((((pb & 7) << 2) | ((pjg >> 1) & 3)) << 2)
                  + ((pb >> 3) | (((pjg >> 3) & 1) << 1));

    // D frag coords: m0 = lane>>2, c0 = (lane&3)*2 (virtual cols within frag)
    const int m0 = lane >> 2;
    const int c0 = (lane & 3) * 2;

    float hold0 = 0.f, hold1 = 0.f;     // register-carried state (h0 = 0)

    for (int t = 0; t < T_STEPS; t++) {
        // prefetch z (overlaps with MMA)
        float zv0 = __ldcg(g_z + ((size_t)t * NU + pjg) * NBATCH + pbg);
        float zv1 = __ldcg(g_z + ((size_t)t * NU + pjg + 1) * NBATCH + pbg);

        // ---- MMA mainloop: 2 independent frags x 16 kt (chain depth 48) -----
        float f0d0 = 0.f, f0d1 = 0.f, f0d2 = 0.f, f0d3 = 0.f;
        float f1d0 = 0.f, f1d1 = 0.f, f1d2 = 0.f, f1d3 = 0.f;
        #pragma unroll
        for (int i = 0; i < 16; i++) {
            int kt = kt0 + i;
            uint4 aH = *(const uint4*)&hfH[(kt * 32 + lane) * 4];
            uint4 aL = *(const uint4*)&hfL[(kt * 32 + lane) * 4];
            mma16816(f0d0, f0d1, f0d2, f0d3, aH.x, aH.y, aH.z, aH.w, wH[0][i][0], wH[0][i][1]);
            mma16816(f1d0, f1d1, f1d2, f1d3, aH.x, aH.y, aH.z, aH.w, wH[1][i][0], wH[1][i][1]);
            mma16816(f0d0, f0d1, f0d2, f0d3, aL.x, aL.y, aL.z, aL.w, wH[0][i][0], wH[0][i][1]);
            mma16816(f1d0, f1d1, f1d2, f1d3, aL.x, aL.y, aL.z, aL.w, wH[1][i][0], wH[1][i][1]);
            mma16816(f0d0, f0d1, f0d2, f0d3, aH.x, aH.y, aH.z, aH.w, wL[0][i][0], wL[0][i][1]);
            mma16816(f1d0, f1d1, f1d2, f1d3, aH.x, aH.y, aH.z, aH.w, wL[1][i][0], wL[1][i][1]);
        }

        // ---- stage D (per K-half buffers) -----------------------------------
        // frag f covers actual cols jd = cg*8 + f*4 + (c0&3), A' if c0<4 else W
        {
            float* s0 = (c0 < 4) ? stgA[kh] : stgW[kh];
            int jd0 = cg * 8 + 0 * 4 + (c0 & 3);
            s0[jd0 * 17 + m0]           = f0d0;
            s0[(jd0 + 1) * 17 + m0]     = f0d1;
            s0[jd0 * 17 + m0 + 8]       = f0d2;
            s0[(jd0 + 1) * 17 + m0 + 8] = f0d3;
            int jd1 = cg * 8 + 1 * 4 + (c0 & 3);
            s0[jd1 * 17 + m0]           = f1d0;
            s0[(jd1 + 1) * 17 + m0]     = f1d1;
            s0[jd1 * 17 + m0 + 8]       = f1d2;
            s0[(jd1 + 1) * 17 + m0 + 8] = f1d3;
        }
        __syncthreads();

        // ---- pointwise update (sum K halves) + frag conversion --------------
        {
            float da0 = stgA[0][pj0 * 17 + pb] + stgA[1][pj0 * 17 + pb];
            float dw0 = stgW[0][pj0 * 17 + pb] + stgW[1][pj0 * 17 + pb];
            float da1 = stgA[0][(pj0 + 1) * 17 + pb] + stgA[1][(pj0 + 1) * 17 + pb];
            float dw1 = stgW[0][(pj0 + 1) * 17 + pb] + stgW[1][(pj0 + 1) * 17 + pb];
            hold0 = hold0 + da0 + EPSF * tanhf(dw0 + zv0);
            hold1 = hold1 + da1 + EPSF * tanhf(dw1 + zv1);
            __nv_bfloat162 hi = __float22bfloat162_rn(make_float2(hold0, hold1));
            __nv_bfloat162 lo = __float22bfloat162_rn(
                make_float2(hold0 - __low2float(hi), hold1 - __high2float(hi)));
            uint2 wv;
            wv.x = *reinterpret_cast<unsigned*>(&hi);
            wv.y = *reinterpret_cast<unsigned*>(&lo);
            g_hf[t & 1][bb][wdx] = wv;
            if (t == T_STEPS - 1) {
                *(float2*)(g_h + HSZ + (size_t)pbg * NU + pjg) = make_float2(hold0, hold1);
            }
        }

        if (CLU) {
            asm volatile("barrier.cluster.arrive.aligned;" ::: "memory");
            asm volatile("barrier.cluster.wait.aligned;" ::: "memory");
        } else {
            grid_barrier();
        }

        // ---- reload frag tiles: pure copy (no conversion) -------------------
        if (t < T_STEPS - 1) {
            const uint2* src = &g_hf[t & 1][bb][0];
            #pragma unroll
            for (int it = 0; it < 16; it++) {
                int wd = it * 256 + tid;
                uint2 v = __ldcg(src + wd);
                hfH[wd] = v.x;
                hfL[wd] = v.y;
            }
        }
        __syncthreads();
    }

    // ---------------- epilogue: out[b] = h_final[b] @ Dw + Db ----------------
    {
        const int b = cta;
        const float* hf = g_h + HSZ + (size_t)b * NU;
        float part[10];
        #pragma unroll
        for (int c = 0; c < 10; c++) part[c] = 0.f;
        for (int k = tid; k < NU; k += 256) {
            float hv = __ldcg(hf + k);
            #pragma unroll
            for (int c = 0; c < 10; c++) part[c] += hv * Dw[k * 10 + c];
        }
        __syncthreads();
        float* red = (float*)hfH;   // reuse frag region (16KB)
        #pragma unroll
        for (int c = 0; c < 10; c++) red[c * 256 + tid] = part[c];
        __syncthreads();
        if (tid < 10) {
            float s = Db[tid];
            for (int i = 0; i < 256; i++) s += red[tid * 256 + i];
            out[b * 10 + tid] = s;
        }
    }
}

// ---------------- launch ------------------------------------------------------
extern "C" void kernel_launch(void* const* d_in, const int* in_sizes, int n_in,
                              void* d_out, int out_size) {
    const float* x  = (const float*)d_in[0];
    const float* B  = (const float*)d_in[1];
    const float* C  = (const float*)d_in[2];
    const float* Ew = (const float*)d_in[3];
    const float* Eb = (const float*)d_in[4];
    const float* Dw = (const float*)d_in[5];
    const float* Db = (const float*)d_in[6];
    float* outp = (float*)d_out;

    cudaFuncSetAttribute(z_kernel, cudaFuncAttributeMaxDynamicSharedMemorySize, Z_SMEM);
    cudaFuncSetAttribute(scan_kernel<true>, cudaFuncAttributeNonPortableClusterSizeAllowed, 1);

    z_kernel<<<T_STEPS, 256, Z_SMEM>>>(x, Ew, Eb);

    cudaLaunchConfig_t cfg = {};
    cfg.gridDim  = dim3(SCAN_CTAS, 1, 1);
    cfg.blockDim = dim3(256, 1, 1);
    cfg.dynamicSmemBytes = 0;
    cfg.stream = 0;
    cudaLaunchAttribute at[1];
    at[0].id = cudaLaunchAttributeClusterDimension;
    at[0].val.clusterDim.x = 16;
    at[0].val.clusterDim.y = 1;
    at[0].val.clusterDim.z = 1;
    cfg.attrs = at;
    cfg.numAttrs = 1;

    int ncl = 0;
    cudaError_t qe = cudaOccupancyMaxActiveClusters(&ncl, scan_kernel<true>, &cfg);
    if (qe == cudaSuccess && ncl >= 1) {
        cudaLaunchKernelEx(&cfg, scan_kernel<true>, B, C, Dw, Db, outp);
    } else {
        cudaGetLastError();
        scan_kernel<false><<<SCAN_CTAS, 256>>>(B, C, Dw, Db, outp);
    }
}

// round 13
// speedup vs baseline: 1.8388x; 1.1403x over previous
#include <cuda_runtime.h>
#include <cuda_bf16.h>
#include <math.h>
#include <stdint.h>

#define T_STEPS 1024
#define NBATCH  128
#define NU      512
#define DIN     128
#define EPSF    0.01f
#define SCAN_CTAS 128
#define HSZ     (NBATCH * NU)
#define Z_SMEM (128 * 132 * 4 + 128 * 64 * 4)

// ---------------- device scratch --------------------------------------------
__device__ float g_z[(size_t)T_STEPS * NU * NBATCH];  // [t][j][b]
__device__ float g_h[2 * HSZ];                        // fp32 h (epilogue only)
__device__ unsigned g_hf[2][8][4096];                 // frag exchange (hi only)
__device__ unsigned g_bar_count;
__device__ volatile unsigned g_bar_phase;

// ---------------- fallback grid barrier --------------------------------------
__device__ __forceinline__ void grid_barrier() {
    __syncthreads();
    if (threadIdx.x == 0) {
        unsigned ph = g_bar_phase;
        __threadfence();
        if (atomicAdd(&g_bar_count, 1u) == SCAN_CTAS - 1u) {
            atomicExch(&g_bar_count, 0u);
            __threadfence();
            g_bar_phase = ph + 1u;
        } else {
            while (g_bar_phase == ph) { __nanosleep(32); }
        }
        __threadfence();
    }
    __syncthreads();
}

// ---------------- z precompute: z[t][j][b] -----------------------------------
__global__ void __launch_bounds__(256) z_kernel(const float* __restrict__ x,
                                                const float* __restrict__ Ew,
                                                const float* __restrict__ Eb) {
    extern __shared__ float sm[];
    float* xs = sm;              // [128][132]
    float* ew = sm + 128 * 132;  // [128][64]
    const int t   = blockIdx.x;
    const int tid = threadIdx.x;

    for (int idx = tid; idx < 128 * 32; idx += 256) {
        int b  = idx >> 5;
        int kq = idx & 31;
        float4 v = *(const float4*)(x + ((size_t)b * T_STEPS + t) * DIN + kq * 4);
        *(float4*)(xs + b * 132 + kq * 4) = v;
    }

    const int bg = tid >> 3;
    const int jg = tid & 7;
    const int b0 = bg * 4;
    const int j0 = jg * 8;

    for (int jb = 0; jb < 8; jb++) {
        __syncthreads();
        for (int idx = tid; idx < 128 * 16; idx += 256) {
            int k  = idx >> 4;
            int jq = idx & 15;
            *(float4*)(ew + k * 64 + jq * 4) =
                *(const float4*)(Ew + (size_t)k * NU + jb * 64 + jq * 4);
        }
        __syncthreads();

        float acc[4][8];
        #pragma unroll
        for (int r = 0; r < 4; r++)
            #pragma unroll
            for (int jj = 0; jj < 8; jj++) acc[r][jj] = 0.f;

        #pragma unroll 2
        for (int k = 0; k < 128; k += 4) {
            float4 xv[4];
            #pragma unroll
            for (int r = 0; r < 4; r++)
                xv[r] = *(const float4*)(xs + (b0 + r) * 132 + k);
            #pragma unroll
            for (int kk = 0; kk < 4; kk++) {
                float4 e0 = *(const float4*)(ew + (k + kk) * 64 + j0);
                float4 e1 = *(const float4*)(ew + (k + kk) * 64 + j0 + 4);
                #pragma unroll
                for (int r = 0; r < 4; r++) {
                    float xk = (kk == 0) ? xv[r].x : (kk == 1) ? xv[r].y
                             : (kk == 2) ? xv[r].z : xv[r].w;
                    acc[r][0] += xk * e0.x;  acc[r][1] += xk * e0.y;
                    acc[r][2] += xk * e0.z;  acc[r][3] += xk * e0.w;
                    acc[r][4] += xk * e1.x;  acc[r][5] += xk * e1.y;
                    acc[r][6] += xk * e1.z;  acc[r][7] += xk * e1.w;
                }
            }
        }

        #pragma unroll
        for (int jj = 0; jj < 8; jj++) {
            int j = jb * 64 + j0 + jj;
            float bias = Eb[j];
            float4 v = make_float4(acc[0][jj] + bias, acc[1][jj] + bias,
                                   acc[2][jj] + bias, acc[3][jj] + bias);
            *(float4*)(g_z + ((size_t)t * NU + j) * NBATCH + b0) = v;
        }
    }
}

// ---------------- HMMA scan: 8 clusters x 16 CTAs, 256 threads ---------------
// R12 structure; ONE change: h-lo compensation term dropped.
//   D = aH*(wH + wL)  -> 4 MMAs per kt per warp (was 6), hfL deleted,
//   exchange word is 4B (hi only).
__device__ __forceinline__ void mma16816(float& d0, float& d1, float& d2, float& d3,
                                         unsigned a0, unsigned a1, unsigned a2, unsigned a3,
                                         unsigned b0, unsigned b1) {
    asm volatile(
        "mma.sync.aligned.m16n8k16.row.col.f32.bf16.bf16.f32 "
        "{%0,%1,%2,%3}, {%4,%5,%6,%7}, {%8,%9}, {%0,%1,%2,%3};"
        : "+f"(d0), "+f"(d1), "+f"(d2), "+f"(d3)
        : "r"(a0), "r"(a1), "r"(a2), "r"(a3), "r"(b0), "r"(b1));
}

template <bool CLU>
__global__ void __launch_bounds__(256, 1) scan_kernel(const float* __restrict__ Bm,
                                                      const float* __restrict__ Cm,
                                                      const float* __restrict__ Dw,
                                                      const float* __restrict__ Db,
                                                      float* __restrict__ out) {
    __shared__ float    stgA[2][32 * 17];    // [kh][j_local][b] A' partials
    __shared__ float    stgW[2][32 * 17];    // [kh][j_local][b] W partials
    __shared__ unsigned hfH[4096];           // h hi frags [kt][lane][reg]

    const int cta  = blockIdx.x;
    const int bb   = cta >> 4;
    const int col0 = (cta & 15) * 32;
    const int tid  = threadIdx.x;
    const int w    = tid >> 5;
    const int lane = tid & 31;
    const int cg   = w >> 1;
    const int kh   = w & 1;
    const int kt0  = kh * 16;

    // ---- build this thread's weight B-fragments (2 frags x 16 kt) -----------
    const int nv  = lane >> 2;          // 0..7 virtual col
    const int mat = nv >> 2;            // 0: A', 1: W
    unsigned wH[2][16][2], wL[2][16][2];
    #pragma unroll
    for (int f = 0; f < 2; f++) {
        const int jw = col0 + cg * 8 + f * 4 + (nv & 3);
        #pragma unroll
        for (int i = 0; i < 16; i++) {
            int kt = kt0 + i;
            #pragma unroll
            for (int r = 0; r < 2; r++) {
                float v[2];
                #pragma unroll
                for (int e = 0; e < 2; e++) {
                    int k = kt * 16 + r * 8 + (lane & 3) * 2 + e;
                    float d = (k == jw) ? 0.01f : 0.0f;
                    v[e] = (mat == 0)
                         ? EPSF * (Bm[(size_t)k * NU + jw] - 0.6f * Bm[(size_t)jw * NU + k] - d)
                         : (Cm[(size_t)k * NU + jw] - 0.6f * Cm[(size_t)jw * NU + k] - d);
                }
                __nv_bfloat162 hi = __float22bfloat162_rn(make_float2(v[0], v[1]));
                float2 hf = make_float2(__low2float(hi), __high2float(hi));
                __nv_bfloat162 lo = __float22bfloat162_rn(make_float2(v[0] - hf.x, v[1] - hf.y));
                wH[f][i][r] = *reinterpret_cast<unsigned*>(&hi);
                wL[f][i][r] = *reinterpret_cast<unsigned*>(&lo);
            }
        }
    }

    // ---- init: zero h frag tile (h0 = 0) ------------------------------------
    for (int i = tid; i < 4096; i += 256) hfH[i] = 0u;
    __syncthreads();

    // pointwise ownership (R10): thread -> (b = tid>>4, j0 = (tid&15)*2)
    const int pb  = tid >> 4;
    const int pj0 = (tid & 15) * 2;
    const int pbg = bb * 16 + pb;
    const int pjg = col0 + pj0;

    // frag word index for this thread's (pb, pjg) pair (R10-verified inverse)
    const int wdx = (pjg >> 4) * 128
                  + ((((pb & 7) << 2) | ((pjg >> 1) & 3)) << 2)
                  + ((pb >> 3) | (((pjg >> 3) & 1) << 1));

    // D frag coords
    const int m0 = lane >> 2;
    const int c0 = (lane & 3) * 2;

    float hold0 = 0.f, hold1 = 0.f;     // register-carried state (h0 = 0)

    for (int t = 0; t < T_STEPS; t++) {
        // prefetch z (overlaps with MMA)
        float zv0 = __ldcg(g_z + ((size_t)t * NU + pjg) * NBATCH + pbg);
        float zv1 = __ldcg(g_z + ((size_t)t * NU + pjg + 1) * NBATCH + pbg);

        // ---- MMA mainloop: 2 frags x 16 kt x 2 terms (aH*wH + aH*wL) --------
        float f0d0 = 0.f, f0d1 = 0.f, f0d2 = 0.f, f0d3 = 0.f;
        float f1d0 = 0.f, f1d1 = 0.f, f1d2 = 0.f, f1d3 = 0.f;
        #pragma unroll
        for (int i = 0; i < 16; i++) {
            int kt = kt0 + i;
            uint4 aH = *(const uint4*)&hfH[(kt * 32 + lane) * 4];
            mma16816(f0d0, f0d1, f0d2, f0d3, aH.x, aH.y, aH.z, aH.w, wH[0][i][0], wH[0][i][1]);
            mma16816(f1d0, f1d1, f1d2, f1d3, aH.x, aH.y, aH.z, aH.w, wH[1][i][0], wH[1][i][1]);
            mma16816(f0d0, f0d1, f0d2, f0d3, aH.x, aH.y, aH.z, aH.w, wL[0][i][0], wL[0][i][1]);
            mma16816(f1d0, f1d1, f1d2, f1d3, aH.x, aH.y, aH.z, aH.w, wL[1][i][0], wL[1][i][1]);
        }

        // ---- stage D (per K-half buffers) -----------------------------------
        {
            float* s0 = (c0 < 4) ? stgA[kh] : stgW[kh];
            int jd0 = cg * 8 + 0 * 4 + (c0 & 3);
            s0[jd0 * 17 + m0]           = f0d0;
            s0[(jd0 + 1) * 17 + m0]     = f0d1;
            s0[jd0 * 17 + m0 + 8]       = f0d2;
            s0[(jd0 + 1) * 17 + m0 + 8] = f0d3;
            int jd1 = cg * 8 + 1 * 4 + (c0 & 3);
            s0[jd1 * 17 + m0]           = f1d0;
            s0[(jd1 + 1) * 17 + m0]     = f1d1;
            s0[jd1 * 17 + m0 + 8]       = f1d2;
            s0[(jd1 + 1) * 17 + m0 + 8] = f1d3;
        }
        __syncthreads();

        // ---- pointwise update (sum K halves) + hi-only frag conversion ------
        {
            float da0 = stgA[0][pj0 * 17 + pb] + stgA[1][pj0 * 17 + pb];
            float dw0 = stgW[0][pj0 * 17 + pb] + stgW[1][pj0 * 17 + pb];
            float da1 = stgA[0][(pj0 + 1) * 17 + pb] + stgA[1][(pj0 + 1) * 17 + pb];
            float dw1 = stgW[0][(pj0 + 1) * 17 + pb] + stgW[1][(pj0 + 1) * 17 + pb];
            hold0 = hold0 + da0 + EPSF * tanhf(dw0 + zv0);
            hold1 = hold1 + da1 + EPSF * tanhf(dw1 + zv1);
            __nv_bfloat162 hi = __float22bfloat162_rn(make_float2(hold0, hold1));
            g_hf[t & 1][bb][wdx] = *reinterpret_cast<unsigned*>(&hi);
            if (t == T_STEPS - 1) {
                *(float2*)(g_h + HSZ + (size_t)pbg * NU + pjg) = make_float2(hold0, hold1);
            }
        }

        if (CLU) {
            asm volatile("barrier.cluster.arrive.aligned;" ::: "memory");
            asm volatile("barrier.cluster.wait.aligned;" ::: "memory");
        } else {
            grid_barrier();
        }

        // ---- reload frag tile: pure copy (vectorized) -----------------------
        if (t < T_STEPS - 1) {
            const uint4* src = (const uint4*)&g_hf[t & 1][bb][0];
            uint4* dst4 = (uint4*)hfH;
            #pragma unroll
            for (int it = 0; it < 4; it++) {
                int wd = it * 256 + tid;
                dst4[wd] = __ldcg(src + wd);
            }
        }
        __syncthreads();
    }

    // ---------------- epilogue: out[b] = h_final[b] @ Dw + Db ----------------
    {
        const int b = cta;
        const float* hf = g_h + HSZ + (size_t)b * NU;
        float part[10];
        #pragma unroll
        for (int c = 0; c < 10; c++) part[c] = 0.f;
        for (int k = tid; k < NU; k += 256) {
            float hv = __ldcg(hf + k);
            #pragma unroll
            for (int c = 0; c < 10; c++) part[c] += hv * Dw[k * 10 + c];
        }
        __syncthreads();
        __shared__ float red[10 * 256];
        #pragma unroll
        for (int c = 0; c < 10; c++) red[c * 256 + tid] = part[c];
        __syncthreads();
        if (tid < 10) {
            float s = Db[tid];
            for (int i = 0; i < 256; i++) s += red[tid * 256 + i];
            out[b * 10 + tid] = s;
        }
    }
}

// ---------------- launch ------------------------------------------------------
extern "C" void kernel_launch(void* const* d_in, const int* in_sizes, int n_in,
                              void* d_out, int out_size) {
    const float* x  = (const float*)d_in[0];
    const float* B  = (const float*)d_in[1];
    const float* C  = (const float*)d_in[2];
    const float* Ew = (const float*)d_in[3];
    const float* Eb = (const float*)d_in[4];
    const float* Dw = (const float*)d_in[5];
    const float* Db = (const float*)d_in[6];
    float* outp = (float*)d_out;

    cudaFuncSetAttribute(z_kernel, cudaFuncAttributeMaxDynamicSharedMemorySize, Z_SMEM);
    cudaFuncSetAttribute(scan_kernel<true>, cudaFuncAttributeNonPortableClusterSizeAllowed, 1);

    z_kernel<<<T_STEPS, 256, Z_SMEM>>>(x, Ew, Eb);

    cudaLaunchConfig_t cfg = {};
    cfg.gridDim  = dim3(SCAN_CTAS, 1, 1);
    cfg.blockDim = dim3(256, 1, 1);
    cfg.dynamicSmemBytes = 0;
    cfg.stream = 0;
    cudaLaunchAttribute at[1];
    at[0].id = cudaLaunchAttributeClusterDimension;
    at[0].val.clusterDim.x = 16;
    at[0].val.clusterDim.y = 1;
    at[0].val.clusterDim.z = 1;
    cfg.attrs = at;
    cfg.numAttrs = 1;

    int ncl = 0;
    cudaError_t qe = cudaOccupancyMaxActiveClusters(&ncl, scan_kernel<true>, &cfg);
    if (qe == cudaSuccess && ncl >= 1) {
        cudaLaunchKernelEx(&cfg, scan_kernel<true>, B, C, Dw, Db, outp);
    } else {
        cudaGetLastError();
        scan_kernel<false><<<SCAN_CTAS, 256>>>(B, C, Dw, Db, outp);
    }
}

// round 14
// speedup vs baseline: 1.9289x; 1.0490x over previous
#include <cuda_runtime.h>
#include <cuda_bf16.h>
#include <math.h>
#include <stdint.h>

#define T_STEPS 1024
#define NBATCH  128
#define NU      512
#define DIN     128
#define EPSF    0.01f
#define SCAN_CTAS 128
#define HSZ     (NBATCH * NU)
#define Z_SMEM (128 * 132 * 4 + 128 * 64 * 4)

// ---------------- device scratch --------------------------------------------
__device__ float g_z[(size_t)T_STEPS * NU * NBATCH];  // [t][j][b]
__device__ float g_h[2 * HSZ];                        // fp32 h (epilogue only)
__device__ unsigned g_hf[2][8][4096];                 // frag exchange (hi only)
__device__ unsigned g_bar_count;
__device__ volatile unsigned g_bar_phase;

// ---------------- fallback grid barrier --------------------------------------
__device__ __forceinline__ void grid_barrier() {
    __syncthreads();
    if (threadIdx.x == 0) {
        unsigned ph = g_bar_phase;
        __threadfence();
        if (atomicAdd(&g_bar_count, 1u) == SCAN_CTAS - 1u) {
            atomicExch(&g_bar_count, 0u);
            __threadfence();
            g_bar_phase = ph + 1u;
        } else {
            while (g_bar_phase == ph) { __nanosleep(32); }
        }
        __threadfence();
    }
    __syncthreads();
}

// ---------------- z precompute: z[t][j][b] -----------------------------------
__global__ void __launch_bounds__(256) z_kernel(const float* __restrict__ x,
                                                const float* __restrict__ Ew,
                                                const float* __restrict__ Eb) {
    extern __shared__ float sm[];
    float* xs = sm;              // [128][132]
    float* ew = sm + 128 * 132;  // [128][64]
    const int t   = blockIdx.x;
    const int tid = threadIdx.x;

    for (int idx = tid; idx < 128 * 32; idx += 256) {
        int b  = idx >> 5;
        int kq = idx & 31;
        float4 v = *(const float4*)(x + ((size_t)b * T_STEPS + t) * DIN + kq * 4);
        *(float4*)(xs + b * 132 + kq * 4) = v;
    }

    const int bg = tid >> 3;
    const int jg = tid & 7;
    const int b0 = bg * 4;
    const int j0 = jg * 8;

    for (int jb = 0; jb < 8; jb++) {
        __syncthreads();
        for (int idx = tid; idx < 128 * 16; idx += 256) {
            int k  = idx >> 4;
            int jq = idx & 15;
            *(float4*)(ew + k * 64 + jq * 4) =
                *(const float4*)(Ew + (size_t)k * NU + jb * 64 + jq * 4);
        }
        __syncthreads();

        float acc[4][8];
        #pragma unroll
        for (int r = 0; r < 4; r++)
            #pragma unroll
            for (int jj = 0; jj < 8; jj++) acc[r][jj] = 0.f;

        #pragma unroll 2
        for (int k = 0; k < 128; k += 4) {
            float4 xv[4];
            #pragma unroll
            for (int r = 0; r < 4; r++)
                xv[r] = *(const float4*)(xs + (b0 + r) * 132 + k);
            #pragma unroll
            for (int kk = 0; kk < 4; kk++) {
                float4 e0 = *(const float4*)(ew + (k + kk) * 64 + j0);
                float4 e1 = *(const float4*)(ew + (k + kk) * 64 + j0 + 4);
                #pragma unroll
                for (int r = 0; r < 4; r++) {
                    float xk = (kk == 0) ? xv[r].x : (kk == 1) ? xv[r].y
                             : (kk == 2) ? xv[r].z : xv[r].w;
                    acc[r][0] += xk * e0.x;  acc[r][1] += xk * e0.y;
                    acc[r][2] += xk * e0.z;  acc[r][3] += xk * e0.w;
                    acc[r][4] += xk * e1.x;  acc[r][5] += xk * e1.y;
                    acc[r][6] += xk * e1.z;  acc[r][7] += xk * e1.w;
                }
            }
        }

        #pragma unroll
        for (int jj = 0; jj < 8; jj++) {
            int j = jb * 64 + j0 + jj;
            float bias = Eb[j];
            float4 v = make_float4(acc[0][jj] + bias, acc[1][jj] + bias,
                                   acc[2][jj] + bias, acc[3][jj] + bias);
            *(float4*)(g_z + ((size_t)t * NU + j) * NBATCH + b0) = v;
        }
    }
}

// ---------------- HMMA scan: 8 clusters x 16 CTAs, 256 threads ---------------
// Warp w (0..7): actual cols jf = col0 + w*4 .. +3 over FULL K.
// Frag vcols n=0..3 -> A' cols, n=4..7 -> W cols. 64 MMA/warp (wH + wL terms).
// Pointwise done WARP-LOCALLY via xor-2 shuffles (no staging smem, no syncs):
//   A-threads (lane&3<2) keep row m0, W-threads keep row m0+8.
__device__ __forceinline__ void mma16816(float& d0, float& d1, float& d2, float& d3,
                                         unsigned a0, unsigned a1, unsigned a2, unsigned a3,
                                         unsigned b0, unsigned b1) {
    asm volatile(
        "mma.sync.aligned.m16n8k16.row.col.f32.bf16.bf16.f32 "
        "{%0,%1,%2,%3}, {%4,%5,%6,%7}, {%8,%9}, {%0,%1,%2,%3};"
        : "+f"(d0), "+f"(d1), "+f"(d2), "+f"(d3)
        : "r"(a0), "r"(a1), "r"(a2), "r"(a3), "r"(b0), "r"(b1));
}

template <bool CLU>
__global__ void __launch_bounds__(256, 1) scan_kernel(const float* __restrict__ Bm,
                                                      const float* __restrict__ Cm,
                                                      const float* __restrict__ Dw,
                                                      const float* __restrict__ Db,
                                                      float* __restrict__ out) {
    __shared__ unsigned hfH[4096];           // h hi frags [kt][lane][reg]
    __shared__ float    red[10 * 256];       // epilogue reduction

    const int cta  = blockIdx.x;
    const int bb   = cta >> 4;
    const int col0 = (cta & 15) * 32;
    const int tid  = threadIdx.x;
    const int w    = tid >> 5;
    const int lane = tid & 31;

    // ---- build this thread's weight B-fragments (1 frag x 32 kt, hi/lo) -----
    const int nv  = lane >> 2;          // 0..7 virtual col
    const int mat = nv >> 2;            // 0: A', 1: W
    const int jw  = col0 + w * 4 + (nv & 3);
    unsigned wH[32][2], wL[32][2];
    #pragma unroll
    for (int i = 0; i < 32; i++) {
        #pragma unroll
        for (int r = 0; r < 2; r++) {
            float v[2];
            #pragma unroll
            for (int e = 0; e < 2; e++) {
                int k = i * 16 + r * 8 + (lane & 3) * 2 + e;
                float d = (k == jw) ? 0.01f : 0.0f;
                v[e] = (mat == 0)
                     ? EPSF * (Bm[(size_t)k * NU + jw] - 0.6f * Bm[(size_t)jw * NU + k] - d)
                     : (Cm[(size_t)k * NU + jw] - 0.6f * Cm[(size_t)jw * NU + k] - d);
            }
            __nv_bfloat162 hi = __float22bfloat162_rn(make_float2(v[0], v[1]));
            float2 hf = make_float2(__low2float(hi), __high2float(hi));
            __nv_bfloat162 lo = __float22bfloat162_rn(make_float2(v[0] - hf.x, v[1] - hf.y));
            wH[i][r] = *reinterpret_cast<unsigned*>(&hi);
            wL[i][r] = *reinterpret_cast<unsigned*>(&lo);
        }
    }

    // ---- init: zero h frag tile (h0 = 0) ------------------------------------
    for (int i = tid; i < 4096; i += 256) hfH[i] = 0u;
    __syncthreads();

    // ---- pointwise ownership (warp-local) -----------------------------------
    const int m0    = lane >> 2;
    const int isW   = (lane & 3) >> 1;          // 0: A-thread, 1: W-thread
    const int pbl   = m0 + isW * 8;             // local row 0..15
    const int pbg   = bb * 16 + pbl;            // global batch row
    const int pj0   = w * 4 + (lane & 1) * 2;   // local col (even)
    const int pjg   = col0 + pj0;               // global col

    // frag word index (R10-verified inverse map) for (pbl, pjg)
    const int wdx = (pjg >> 4) * 128
                  + ((((pbl & 7) << 2) | ((pjg >> 1) & 3)) << 2)
                  + ((pbl >> 3) | (((pjg >> 3) & 1) << 1));

    float hold0 = 0.f, hold1 = 0.f;     // register-carried state (h0 = 0)

    // z prefetch pipeline: fetch step-0 operands now
    float zn0 = __ldcg(g_z + ((size_t)0 * NU + pjg) * NBATCH + pbg);
    float zn1 = __ldcg(g_z + ((size_t)0 * NU + pjg + 1) * NBATCH + pbg);

    for (int t = 0; t < T_STEPS; t++) {
        float zv0 = zn0, zv1 = zn1;
        if (t < T_STEPS - 1) {          // prefetch NEXT step's z (crosses barrier)
            zn0 = __ldcg(g_z + ((size_t)(t + 1) * NU + pjg) * NBATCH + pbg);
            zn1 = __ldcg(g_z + ((size_t)(t + 1) * NU + pjg + 1) * NBATCH + pbg);
        }

        // ---- MMA mainloop: 4 chains (wH/wL x even/odd kt), depth 16 ---------
        float hA0 = 0.f, hA1 = 0.f, hA2 = 0.f, hA3 = 0.f;
        float hB0 = 0.f, hB1 = 0.f, hB2 = 0.f, hB3 = 0.f;
        float lA0 = 0.f, lA1 = 0.f, lA2 = 0.f, lA3 = 0.f;
        float lB0 = 0.f, lB1 = 0.f, lB2 = 0.f, lB3 = 0.f;
        #pragma unroll
        for (int i = 0; i < 16; i++) {
            int k0 = i * 2, k1 = i * 2 + 1;
            uint4 a0 = *(const uint4*)&hfH[(k0 * 32 + lane) * 4];
            uint4 a1 = *(const uint4*)&hfH[(k1 * 32 + lane) * 4];
            mma16816(hA0, hA1, hA2, hA3, a0.x, a0.y, a0.z, a0.w, wH[k0][0], wH[k0][1]);
            mma16816(hB0, hB1, hB2, hB3, a1.x, a1.y, a1.z, a1.w, wH[k1][0], wH[k1][1]);
            mma16816(lA0, lA1, lA2, lA3, a0.x, a0.y, a0.z, a0.w, wL[k0][0], wL[k0][1]);
            mma16816(lB0, lB1, lB2, lB3, a1.x, a1.y, a1.z, a1.w, wL[k1][0], wL[k1][1]);
        }
        float d0 = (hA0 + hB0) + (lA0 + lB0);
        float d1 = (hA1 + hB1) + (lA1 + lB1);
        float d2 = (hA2 + hB2) + (lA2 + lB2);
        float d3 = (hA3 + hB3) + (lA3 + lB3);

        // ---- warp-local A/W exchange: xor-2 shuffle -------------------------
        // A-thread sends its row-(m0+8) A pair, receives partner's row-m0 W pair.
        // W-thread sends its row-m0 W pair, receives partner's row-(m0+8) A pair.
        float sx = isW ? d0 : d2;
        float sy = isW ? d1 : d3;
        float rx = __shfl_xor_sync(0xffffffffu, sx, 2);
        float ry = __shfl_xor_sync(0xffffffffu, sy, 2);
        float a0v = isW ? rx : d0;
        float a1v = isW ? ry : d1;
        float w0v = isW ? d2 : rx;
        float w1v = isW ? d3 : ry;

        // ---- pointwise update + hi frag conversion + exchange store ---------
        hold0 = hold0 + a0v + EPSF * tanhf(w0v + zv0);
        hold1 = hold1 + a1v + EPSF * tanhf(w1v + zv1);
        {
            __nv_bfloat162 hi = __float22bfloat162_rn(make_float2(hold0, hold1));
            g_hf[t & 1][bb][wdx] = *reinterpret_cast<unsigned*>(&hi);
        }
        if (t == T_STEPS - 1) {
            *(float2*)(g_h + HSZ + (size_t)pbg * NU + pjg) = make_float2(hold0, hold1);
        }

        if (CLU) {
            asm volatile("barrier.cluster.arrive.aligned;" ::: "memory");
            asm volatile("barrier.cluster.wait.aligned;" ::: "memory");
        } else {
            grid_barrier();
        }

        // ---- reload frag tile: pure vectorized copy -------------------------
        if (t < T_STEPS - 1) {
            const uint4* src = (const uint4*)&g_hf[t & 1][bb][0];
            uint4* dst4 = (uint4*)hfH;
            #pragma unroll
            for (int it = 0; it < 4; it++) {
                int wd = it * 256 + tid;
                dst4[wd] = __ldcg(src + wd);
            }
        }
        __syncthreads();
    }

    // ---------------- epilogue: out[b] = h_final[b] @ Dw + Db ----------------
    {
        const int b = cta;
        const float* hf = g_h + HSZ + (size_t)b * NU;
        float part[10];
        #pragma unroll
        for (int c = 0; c < 10; c++) part[c] = 0.f;
        for (int k = tid; k < NU; k += 256) {
            float hv = __ldcg(hf + k);
            #pragma unroll
            for (int c = 0; c < 10; c++) part[c] += hv * Dw[k * 10 + c];
        }
        __syncthreads();
        #pragma unroll
        for (int c = 0; c < 10; c++) red[c * 256 + tid] = part[c];
        __syncthreads();
        if (tid < 10) {
            float s = Db[tid];
            for (int i = 0; i < 256; i++) s += red[tid * 256 + i];
            out[b * 10 + tid] = s;
        }
    }
}

// ---------------- launch ------------------------------------------------------
extern "C" void kernel_launch(void* const* d_in, const int* in_sizes, int n_in,
                              void* d_out, int out_size) {
    const float* x  = (const float*)d_in[0];
    const float* B  = (const float*)d_in[1];
    const float* C  = (const float*)d_in[2];
    const float* Ew = (const float*)d_in[3];
    const float* Eb = (const float*)d_in[4];
    const float* Dw = (const float*)d_in[5];
    const float* Db = (const float*)d_in[6];
    float* outp = (float*)d_out;

    cudaFuncSetAttribute(z_kernel, cudaFuncAttributeMaxDynamicSharedMemorySize, Z_SMEM);
    cudaFuncSetAttribute(scan_kernel<true>, cudaFuncAttributeNonPortableClusterSizeAllowed, 1);

    z_kernel<<<T_STEPS, 256, Z_SMEM>>>(x, Ew, Eb);

    cudaLaunchConfig_t cfg = {};
    cfg.gridDim  = dim3(SCAN_CTAS, 1, 1);
    cfg.blockDim = dim3(256, 1, 1);
    cfg.dynamicSmemBytes = 0;
    cfg.stream = 0;
    cudaLaunchAttribute at[1];
    at[0].id = cudaLaunchAttributeClusterDimension;
    at[0].val.clusterDim.x = 16;
    at[0].val.clusterDim.y = 1;
    at[0].val.clusterDim.z = 1;
    cfg.attrs = at;
    cfg.numAttrs = 1;

    int ncl = 0;
    cudaError_t qe = cudaOccupancyMaxActiveClusters(&ncl, scan_kernel<true>, &cfg);
    if (qe == cudaSuccess && ncl >= 1) {
        cudaLaunchKernelEx(&cfg, scan_kernel<true>, B, C, Dw, Db, outp);
    } else {
        cudaGetLastError();
        scan_kernel<false><<<SCAN_CTAS, 256>>>(B, C, Dw, Db, outp);
    }
}

// round 15
// speedup vs baseline: 2.1278x; 1.1031x over previous
#include <cuda_runtime.h>
#include <cuda_bf16.h>
#include <math.h>
#include <stdint.h>

#define T_STEPS 1024
#define NBATCH  128
#define NU      512
#define DIN     128
#define EPSF    0.01f
#define SCAN_CTAS 128
#define HSZ     (NBATCH * NU)

// z HMMA kernel smem: x B-frags hi/lo, 8192 words each
#define ZS_WORDS 8192
#define ZS_SMEM  (2 * ZS_WORDS * 4)    // 65536 B

// ---------------- device scratch --------------------------------------------
__device__ float g_z[(size_t)T_STEPS * NU * NBATCH];  // [t][j][b]
__device__ float g_h[2 * HSZ];                        // fp32 h (epilogue only)
__device__ unsigned g_hf[2][8][4096];                 // frag exchange (hi only)
__device__ unsigned g_bar_count;
__device__ volatile unsigned g_bar_phase;

__device__ __forceinline__ void mma16816(float& d0, float& d1, float& d2, float& d3,
                                         unsigned a0, unsigned a1, unsigned a2, unsigned a3,
                                         unsigned b0, unsigned b1) {
    asm volatile(
        "mma.sync.aligned.m16n8k16.row.col.f32.bf16.bf16.f32 "
        "{%0,%1,%2,%3}, {%4,%5,%6,%7}, {%8,%9}, {%0,%1,%2,%3};"
        : "+f"(d0), "+f"(d1), "+f"(d2), "+f"(d3)
        : "r"(a0), "r"(a1), "r"(a2), "r"(a3), "r"(b0), "r"(b1));
}

// ---------------- fallback grid barrier --------------------------------------
__device__ __forceinline__ void grid_barrier() {
    __syncthreads();
    if (threadIdx.x == 0) {
        unsigned ph = g_bar_phase;
        __threadfence();
        if (atomicAdd(&g_bar_count, 1u) == SCAN_CTAS - 1u) {
            atomicExch(&g_bar_count, 0u);
            __threadfence();
            g_bar_phase = ph + 1u;
        } else {
            while (g_bar_phase == ph) { __nanosleep(32); }
        }
        __threadfence();
    }
    __syncthreads();
}

// ---------------- z HMMA kernel ----------------------------------------------
// CTA = (t = blockIdx.x, jhalf = blockIdx.y). 256 threads, 8 warps.
// Computes z[t][j][b] for j in [jhalf*256, +256), all 128 b.
// A = Ew^T (M=j), B = x_t (N=b), K=128 (8 kt).  3-term compensated bf16:
//   EwH*xH + EwL*xH + EwH*xL  (residual ~2^-18, negligible).
// Warp w owns m-tiles jt = jhalf*16 + w*2 + {0,1}.
__global__ void __launch_bounds__(256) z_kernel(const float* __restrict__ x,
                                                const float* __restrict__ Ew,
                                                const float* __restrict__ Eb) {
    extern __shared__ unsigned zs[];
    unsigned* xsH = zs;              // [nt16][kt8][lane32][r2]
    unsigned* xsL = zs + ZS_WORDS;
    const int t     = blockIdx.x;
    const int jhalf = blockIdx.y;
    const int tid   = threadIdx.x;
    const int w     = tid >> 5;
    const int lane  = tid & 31;

    // ---- stage x_t as B-frags (hi/lo) ---------------------------------------
    // pair (b, kp): k = 2*kp; frag word: nt=b>>3, lane = (b&7)*4 + (kp&3),
    // kt = kp>>3, r = (kp>>2)&1
    for (int p = tid; p < 128 * 64; p += 256) {
        int b  = p >> 6;
        int kp = p & 63;
        float2 xv = *(const float2*)(x + ((size_t)b * T_STEPS + t) * DIN + kp * 2);
        __nv_bfloat162 hi = __float22bfloat162_rn(xv);
        __nv_bfloat162 lo = __float22bfloat162_rn(
            make_float2(xv.x - __low2float(hi), xv.y - __high2float(hi)));
        int idx = (((b >> 3) * 8 + (kp >> 3)) * 32 + (b & 7) * 4 + (kp & 3)) * 2 + ((kp >> 2) & 1);
        xsH[idx] = *reinterpret_cast<unsigned*>(&hi);
        xsL[idx] = *reinterpret_cast<unsigned*>(&lo);
    }

    // ---- build Ew A-frags in registers (2 m-tiles x 8 kt x 4 regs, hi/lo) ---
    unsigned eH[2][8][4], eL[2][8][4];
    float ebv[2][2];   // Eb for (mt, row-half)
    #pragma unroll
    for (int mt = 0; mt < 2; mt++) {
        const int jbase = (jhalf * 16 + w * 2 + mt) * 16;
        ebv[mt][0] = Eb[jbase + (lane >> 2)];
        ebv[mt][1] = Eb[jbase + (lane >> 2) + 8];
        #pragma unroll
        for (int kt = 0; kt < 8; kt++) {
            #pragma unroll
            for (int r = 0; r < 4; r++) {
                int j = jbase + (lane >> 2) + 8 * (r & 1);
                int k = kt * 16 + (lane & 3) * 2 + 8 * (r >> 1);
                float v0 = Ew[(size_t)k * NU + j];
                float v1 = Ew[(size_t)(k + 1) * NU + j];
                __nv_bfloat162 hi = __float22bfloat162_rn(make_float2(v0, v1));
                __nv_bfloat162 lo = __float22bfloat162_rn(
                    make_float2(v0 - __low2float(hi), v1 - __high2float(hi)));
                eH[mt][kt][r] = *reinterpret_cast<unsigned*>(&hi);
                eL[mt][kt][r] = *reinterpret_cast<unsigned*>(&lo);
            }
        }
    }
    __syncthreads();

    // ---- main loop over 16 n-blocks (b tiles of 8) --------------------------
    const int jr = lane >> 2;          // D row within tile
    const int bc = (lane & 3) * 2;     // D col pair within n8
    #pragma unroll 1
    for (int nb = 0; nb < 16; nb++) {
        float a00 = 0.f, a01 = 0.f, a02 = 0.f, a03 = 0.f;   // mt 0
        float a10 = 0.f, a11 = 0.f, a12 = 0.f, a13 = 0.f;   // mt 1
        #pragma unroll
        for (int kt = 0; kt < 8; kt++) {
            uint2 bH = *(const uint2*)&xsH[((nb * 8 + kt) * 32 + lane) * 2];
            uint2 bL = *(const uint2*)&xsL[((nb * 8 + kt) * 32 + lane) * 2];
            mma16816(a00, a01, a02, a03, eH[0][kt][0], eH[0][kt][1], eH[0][kt][2], eH[0][kt][3], bH.x, bH.y);
            mma16816(a10, a11, a12, a13, eH[1][kt][0], eH[1][kt][1], eH[1][kt][2], eH[1][kt][3], bH.x, bH.y);
            mma16816(a00, a01, a02, a03, eL[0][kt][0], eL[0][kt][1], eL[0][kt][2], eL[0][kt][3], bH.x, bH.y);
            mma16816(a10, a11, a12, a13, eL[1][kt][0], eL[1][kt][1], eL[1][kt][2], eL[1][kt][3], bH.x, bH.y);
            mma16816(a00, a01, a02, a03, eH[0][kt][0], eH[0][kt][1], eH[0][kt][2], eH[0][kt][3], bL.x, bL.y);
            mma16816(a10, a11, a12, a13, eH[1][kt][0], eH[1][kt][1], eH[1][kt][2], eH[1][kt][3], bL.x, bL.y);
        }
        // store: z[t][j][b], D tile layout d0:(jr,bc) d1:(jr,bc+1) d2:(jr+8,..)
        int b0 = nb * 8 + bc;
        #pragma unroll
        for (int mt = 0; mt < 2; mt++) {
            int jbase = (jhalf * 16 + w * 2 + mt) * 16;
            float d0 = (mt ? a10 : a00) + ebv[mt][0];
            float d1 = (mt ? a11 : a01) + ebv[mt][0];
            float d2 = (mt ? a12 : a02) + ebv[mt][1];
            float d3 = (mt ? a13 : a03) + ebv[mt][1];
            *(float2*)(g_z + ((size_t)t * NU + jbase + jr) * NBATCH + b0)     = make_float2(d0, d1);
            *(float2*)(g_z + ((size_t)t * NU + jbase + jr + 8) * NBATCH + b0) = make_float2(d2, d3);
        }
    }
}

// ---------------- HMMA scan (byte-identical to R14 passing) ------------------
template <bool CLU>
__global__ void __launch_bounds__(256, 1) scan_kernel(const float* __restrict__ Bm,
                                                      const float* __restrict__ Cm,
                                                      const float* __restrict__ Dw,
                                                      const float* __restrict__ Db,
                                                      float* __restrict__ out) {
    __shared__ unsigned hfH[4096];           // h hi frags [kt][lane][reg]
    __shared__ float    red[10 * 256];       // epilogue reduction

    const int cta  = blockIdx.x;
    const int bb   = cta >> 4;
    const int col0 = (cta & 15) * 32;
    const int tid  = threadIdx.x;
    const int w    = tid >> 5;
    const int lane = tid & 31;

    // ---- build this thread's weight B-fragments (1 frag x 32 kt, hi/lo) -----
    const int nv  = lane >> 2;
    const int mat = nv >> 2;
    const int jw  = col0 + w * 4 + (nv & 3);
    unsigned wH[32][2], wL[32][2];
    #pragma unroll
    for (int i = 0; i < 32; i++) {
        #pragma unroll
        for (int r = 0; r < 2; r++) {
            float v[2];
            #pragma unroll
            for (int e = 0; e < 2; e++) {
                int k = i * 16 + r * 8 + (lane & 3) * 2 + e;
                float d = (k == jw) ? 0.01f : 0.0f;
                v[e] = (mat == 0)
                     ? EPSF * (Bm[(size_t)k * NU + jw] - 0.6f * Bm[(size_t)jw * NU + k] - d)
                     : (Cm[(size_t)k * NU + jw] - 0.6f * Cm[(size_t)jw * NU + k] - d);
            }
            __nv_bfloat162 hi = __float22bfloat162_rn(make_float2(v[0], v[1]));
            float2 hf = make_float2(__low2float(hi), __high2float(hi));
            __nv_bfloat162 lo = __float22bfloat162_rn(make_float2(v[0] - hf.x, v[1] - hf.y));
            wH[i][r] = *reinterpret_cast<unsigned*>(&hi);
            wL[i][r] = *reinterpret_cast<unsigned*>(&lo);
        }
    }

    for (int i = tid; i < 4096; i += 256) hfH[i] = 0u;
    __syncthreads();

    const int m0    = lane >> 2;
    const int isW   = (lane & 3) >> 1;
    const int pbl   = m0 + isW * 8;
    const int pbg   = bb * 16 + pbl;
    const int pj0   = w * 4 + (lane & 1) * 2;
    const int pjg   = col0 + pj0;

    const int wdx = (pjg >> 4) * 128
                  + ((((pbl & 7) << 2) | ((pjg >> 1) & 3)) << 2)
                  + ((pbl >> 3) | (((pjg >> 3) & 1) << 1));

    float hold0 = 0.f, hold1 = 0.f;

    float zn0 = __ldcg(g_z + ((size_t)0 * NU + pjg) * NBATCH + pbg);
    float zn1 = __ldcg(g_z + ((size_t)0 * NU + pjg + 1) * NBATCH + pbg);

    for (int t = 0; t < T_STEPS; t++) {
        float zv0 = zn0, zv1 = zn1;
        if (t < T_STEPS - 1) {
            zn0 = __ldcg(g_z + ((size_t)(t + 1) * NU + pjg) * NBATCH + pbg);
            zn1 = __ldcg(g_z + ((size_t)(t + 1) * NU + pjg + 1) * NBATCH + pbg);
        }

        float hA0 = 0.f, hA1 = 0.f, hA2 = 0.f, hA3 = 0.f;
        float hB0 = 0.f, hB1 = 0.f, hB2 = 0.f, hB3 = 0.f;
        float lA0 = 0.f, lA1 = 0.f, lA2 = 0.f, lA3 = 0.f;
        float lB0 = 0.f, lB1 = 0.f, lB2 = 0.f, lB3 = 0.f;
        #pragma unroll
        for (int i = 0; i < 16; i++) {
            int k0 = i * 2, k1 = i * 2 + 1;
            uint4 a0 = *(const uint4*)&hfH[(k0 * 32 + lane) * 4];
            uint4 a1 = *(const uint4*)&hfH[(k1 * 32 + lane) * 4];
            mma16816(hA0, hA1, hA2, hA3, a0.x, a0.y, a0.z, a0.w, wH[k0][0], wH[k0][1]);
            mma16816(hB0, hB1, hB2, hB3, a1.x, a1.y, a1.z, a1.w, wH[k1][0], wH[k1][1]);
            mma16816(lA0, lA1, lA2, lA3, a0.x, a0.y, a0.z, a0.w, wL[k0][0], wL[k0][1]);
            mma16816(lB0, lB1, lB2, lB3, a1.x, a1.y, a1.z, a1.w, wL[k1][0], wL[k1][1]);
        }
        float d0 = (hA0 + hB0) + (lA0 + lB0);
        float d1 = (hA1 + hB1) + (lA1 + lB1);
        float d2 = (hA2 + hB2) + (lA2 + lB2);
        float d3 = (hA3 + hB3) + (lA3 + lB3);

        float sx = isW ? d0 : d2;
        float sy = isW ? d1 : d3;
        float rx = __shfl_xor_sync(0xffffffffu, sx, 2);
        float ry = __shfl_xor_sync(0xffffffffu, sy, 2);
        float a0v = isW ? rx : d0;
        float a1v = isW ? ry : d1;
        float w0v = isW ? d2 : rx;
        float w1v = isW ? d3 : ry;

        hold0 = hold0 + a0v + EPSF * tanhf(w0v + zv0);
        hold1 = hold1 + a1v + EPSF * tanhf(w1v + zv1);
        {
            __nv_bfloat162 hi = __float22bfloat162_rn(make_float2(hold0, hold1));
            g_hf[t & 1][bb][wdx] = *reinterpret_cast<unsigned*>(&hi);
        }
        if (t == T_STEPS - 1) {
            *(float2*)(g_h + HSZ + (size_t)pbg * NU + pjg) = make_float2(hold0, hold1);
        }

        if (CLU) {
            asm volatile("barrier.cluster.arrive.aligned;" ::: "memory");
            asm volatile("barrier.cluster.wait.aligned;" ::: "memory");
        } else {
            grid_barrier();
        }

        if (t < T_STEPS - 1) {
            const uint4* src = (const uint4*)&g_hf[t & 1][bb][0];
            uint4* dst4 = (uint4*)hfH;
            #pragma unroll
            for (int it = 0; it < 4; it++) {
                int wd = it * 256 + tid;
                dst4[wd] = __ldcg(src + wd);
            }
        }
        __syncthreads();
    }

    // ---------------- epilogue ------------------------------------------------
    {
        const int b = cta;
        const float* hf = g_h + HSZ + (size_t)b * NU;
        float part[10];
        #pragma unroll
        for (int c = 0; c < 10; c++) part[c] = 0.f;
        for (int k = tid; k < NU; k += 256) {
            float hv = __ldcg(hf + k);
            #pragma unroll
            for (int c = 0; c < 10; c++) part[c] += hv * Dw[k * 10 + c];
        }
        __syncthreads();
        #pragma unroll
        for (int c = 0; c < 10; c++) red[c * 256 + tid] = part[c];
        __syncthreads();
        if (tid < 10) {
            float s = Db[tid];
            for (int i = 0; i < 256; i++) s += red[tid * 256 + i];
            out[b * 10 + tid] = s;
        }
    }
}

// ---------------- launch ------------------------------------------------------
extern "C" void kernel_launch(void* const* d_in, const int* in_sizes, int n_in,
                              void* d_out, int out_size) {
    const float* x  = (const float*)d_in[0];
    const float* B  = (const float*)d_in[1];
    const float* C  = (const float*)d_in[2];
    const float* Ew = (const float*)d_in[3];
    const float* Eb = (const float*)d_in[4];
    const float* Dw = (const float*)d_in[5];
    const float* Db = (const float*)d_in[6];
    float* outp = (float*)d_out;

    cudaFuncSetAttribute(z_kernel, cudaFuncAttributeMaxDynamicSharedMemorySize, ZS_SMEM);
    cudaFuncSetAttribute(scan_kernel<true>, cudaFuncAttributeNonPortableClusterSizeAllowed, 1);

    z_kernel<<<dim3(T_STEPS, 2), 256, ZS_SMEM>>>(x, Ew, Eb);

    cudaLaunchConfig_t cfg = {};
    cfg.gridDim  = dim3(SCAN_CTAS, 1, 1);
    cfg.blockDim = dim3(256, 1, 1);
    cfg.dynamicSmemBytes = 0;
    cfg.stream = 0;
    cudaLaunchAttribute at[1];
    at[0].id = cudaLaunchAttributeClusterDimension;
    at[0].val.clusterDim.x = 16;
    at[0].val.clusterDim.y = 1;
    at[0].val.clusterDim.z = 1;
    cfg.attrs = at;
    cfg.numAttrs = 1;

    int ncl = 0;
    cudaError_t qe = cudaOccupancyMaxActiveClusters(&ncl, scan_kernel<true>, &cfg);
    if (qe == cudaSuccess && ncl >= 1) {
        cudaLaunchKernelEx(&cfg, scan_kernel<true>, B, C, Dw, Db, outp);
    } else {
        cudaGetLastError();
        scan_kernel<false><<<SCAN_CTAS, 256>>>(B, C, Dw, Db, outp);
    }
}